// round 2
// baseline (speedup 1.0000x reference)
#include <cuda_runtime.h>
#include <math_constants.h>

#define NN 50000
#define NE 1600000
#define FIN 264
#define FH 48
#define FC 144
#define FM 64

// ---------------- scratch (static __device__ globals; no allocs) ----------------
__device__ int   g_is64;
__device__ int   g_row[NE];
__device__ int   g_col[NE];
__device__ float g_deg[NN];                 // degree, then dis (in-place rsqrt)
__device__ int   g_count[NN];
__device__ int   g_off[NN + 1];
__device__ int   g_cursor[NN];
__device__ int2  g_csr[NE];                 // per sorted edge: (src row, norm bits)
__device__ float g_H[(size_t)NN * FC];      // [hM | hA | hS(relu+bias)] per node
__device__ float g_Y[(size_t)NN * FC];      // concat features for MLP
__device__ float g_Wcat[FIN * FC];
__device__ float g_bcat[FC];

// ---------------- dtype detect: int64 edge_index has odd int32 words == 0 ----------------
__global__ void k_detect(const int* __restrict__ ei32) {
    if (threadIdx.x == 0 && blockIdx.x == 0) {
        int all0 = 1;
        for (int k = 0; k < 32; k++)
            if (ei32[2 * k + 1] != 0) { all0 = 0; break; }
        g_is64 = all0;
    }
}

// ---------------- init ----------------
__global__ void k_init() {
    int i = blockIdx.x * blockDim.x + threadIdx.x;
    if (i < NN) { g_deg[i] = 1.0f; g_count[i] = 0; }
}

// ---------------- extract edges (dtype-agnostic) + degree/in-degree histogram ----------------
__global__ void k_edges(const int* __restrict__ ei32, const float* __restrict__ ew) {
    int e = blockIdx.x * blockDim.x + threadIdx.x;
    if (e < NE) {
        int row, col;
        if (g_is64) {
            // int64 little-endian, values < 2^31: low word is the value
            row = ei32[2 * e];
            col = ei32[2 * (NE + e)];
        } else {
            row = ei32[e];
            col = ei32[NE + e];
        }
        g_row[e] = row;
        g_col[e] = col;
        atomicAdd(&g_deg[col], ew[e]);
        atomicAdd(&g_count[col], 1);
    }
}

__global__ void k_dis() {
    int i = blockIdx.x * blockDim.x + threadIdx.x;
    if (i < NN) g_deg[i] = rsqrtf(g_deg[i]);   // deg >= 1 always (self loop weight 1)
}

// ---------------- single-block exclusive scan (50000 elements) ----------------
__global__ void k_scan() {
    __shared__ int s[1024];
    __shared__ int carry;
    int tid = threadIdx.x;
    if (tid == 0) carry = 0;
    __syncthreads();
    for (int base = 0; base < NN; base += 1024) {
        int v = (base + tid < NN) ? g_count[base + tid] : 0;
        s[tid] = v;
        __syncthreads();
        for (int off = 1; off < 1024; off <<= 1) {
            int t = (tid >= off) ? s[tid - off] : 0;
            __syncthreads();
            s[tid] += t;
            __syncthreads();
        }
        int excl = s[tid] - v;
        int c = carry;
        if (base + tid < NN) {
            g_off[base + tid]    = c + excl;
            g_cursor[base + tid] = c + excl;
        }
        __syncthreads();
        if (tid == 1023) carry = c + s[1023];
        __syncthreads();
    }
    if (tid == 0) g_off[NN] = carry;
}

// ---------------- pack weights [WM|WA|WS] and bias (only hS gets bias in GEMM) ----------------
__global__ void k_pack(const float* __restrict__ WM, const float* __restrict__ WA,
                       const float* __restrict__ WS, const float* __restrict__ bS) {
    int idx = blockIdx.x * blockDim.x + threadIdx.x;
    if (idx < FIN * FC) {
        int k = idx / FC, c = idx % FC;
        float v;
        if (c < 48)      v = WM[k * FH + c];
        else if (c < 96) v = WA[k * FH + (c - 48)];
        else             v = WS[k * FH + (c - 96)];
        g_Wcat[idx] = v;
    }
    if (idx < FC) g_bcat[idx] = (idx < 96) ? 0.0f : bS[idx - 96];
}

// ---------------- GEMM1: H = x @ Wcat  (cols>=96 get bias + relu) ----------------
__global__ __launch_bounds__(256) void k_gemm1(const float* __restrict__ x) {
    __shared__ float As[8][128];   // As[k][m]
    __shared__ float Bs[8][144];
    int tid = threadIdx.x;
    int tx = tid & 15, ty = tid >> 4;
    int row0 = blockIdx.x * 128;
    float acc[8][9];
#pragma unroll
    for (int r = 0; r < 8; r++)
#pragma unroll
        for (int c = 0; c < 9; c++) acc[r][c] = 0.f;

    for (int kt = 0; kt < FIN; kt += 8) {
#pragma unroll
        for (int l = 0; l < 4; l++) {
            int idx = tid + l * 256;
            int m = idx >> 3, kk = idx & 7;
            int row = row0 + m;
            As[kk][m] = (row < NN) ? x[(size_t)row * FIN + kt + kk] : 0.f;
        }
        for (int idx = tid; idx < 8 * 144; idx += 256) {
            int kk = idx / 144, c = idx - kk * 144;
            Bs[kk][c] = g_Wcat[(kt + kk) * FC + c];
        }
        __syncthreads();
#pragma unroll
        for (int kk = 0; kk < 8; kk++) {
            float a[8], b[9];
#pragma unroll
            for (int r = 0; r < 8; r++) a[r] = As[kk][ty * 8 + r];
#pragma unroll
            for (int c = 0; c < 9; c++) b[c] = Bs[kk][tx * 9 + c];
#pragma unroll
            for (int r = 0; r < 8; r++)
#pragma unroll
                for (int c = 0; c < 9; c++) acc[r][c] = fmaf(a[r], b[c], acc[r][c]);
        }
        __syncthreads();
    }
#pragma unroll
    for (int r = 0; r < 8; r++) {
        int row = row0 + ty * 8 + r;
        if (row < NN) {
#pragma unroll
            for (int c = 0; c < 9; c++) {
                int col = tx * 9 + c;
                float v = acc[r][c] + g_bcat[col];
                if (col >= 96) v = fmaxf(v, 0.f);
                g_H[(size_t)row * FC + col] = v;
            }
        }
    }
}

// ---------------- CSR scatter: group edges by destination col ----------------
__global__ void k_csr(const float* __restrict__ ew) {
    int e = blockIdx.x * blockDim.x + threadIdx.x;
    if (e < NE) {
        int row = g_row[e];
        int col = g_col[e];
        float nrm = g_deg[row] * ew[e] * g_deg[col];   // g_deg holds dis now
        int pos = atomicAdd(&g_cursor[col], 1);
        g_csr[pos] = make_int2(row, __float_as_int(nrm));
    }
}

// ---------------- aggregation: 1 warp per node, 8 lanes per edge, no atomics ----------------
__global__ __launch_bounds__(256) void k_agg(const float* __restrict__ bM, const float* __restrict__ bA) {
    __shared__ float sb[96];
    int tid = threadIdx.x;
    if (tid < 96) sb[tid] = (tid < 48) ? bM[tid] : bA[tid - 48];
    __syncthreads();

    int wid = tid >> 5;
    int i = blockIdx.x * 8 + wid;          // grid = NN/8 exactly
    int lane = tid & 31;
    int group = lane >> 3;
    int gl = lane & 7;
    bool m1 = (gl < 4);                    // slot1: max for gl<4, add otherwise
    const float NINF = -CUDART_INF_F;

    const float* Hrow = g_H + (size_t)i * FC;
    float4 acc0, acc1, acc2;
    if (group == 0) {
        float dii = g_deg[i];
        float sm = dii * dii;              // self-loop norm
        float4 v0 = *(const float4*)(Hrow + gl * 4);
        float4 v1 = *(const float4*)(Hrow + 32 + gl * 4);
        float4 v2 = *(const float4*)(Hrow + 64 + gl * 4);
        acc0 = make_float4(sm * v0.x, sm * v0.y, sm * v0.z, sm * v0.w);
        acc1 = make_float4(sm * v1.x, sm * v1.y, sm * v1.z, sm * v1.w);
        acc2 = make_float4(sm * v2.x, sm * v2.y, sm * v2.z, sm * v2.w);
    } else {
        acc0 = make_float4(NINF, NINF, NINF, NINF);
        float i1 = m1 ? NINF : 0.f;
        acc1 = make_float4(i1, i1, i1, i1);
        acc2 = make_float4(0.f, 0.f, 0.f, 0.f);
    }

    int s0 = g_off[i], s1 = g_off[i + 1];
    for (int j = s0 + group; j < s1; j += 4) {
        int2 p = g_csr[j];
        const float* Hr = g_H + (size_t)p.x * FC;
        float nrm = __int_as_float(p.y);
        float4 v0 = *(const float4*)(Hr + gl * 4);
        float4 v1 = *(const float4*)(Hr + 32 + gl * 4);
        float4 v2 = *(const float4*)(Hr + 64 + gl * 4);
        acc0.x = fmaxf(acc0.x, nrm * v0.x); acc0.y = fmaxf(acc0.y, nrm * v0.y);
        acc0.z = fmaxf(acc0.z, nrm * v0.z); acc0.w = fmaxf(acc0.w, nrm * v0.w);
        if (m1) {
            acc1.x = fmaxf(acc1.x, nrm * v1.x); acc1.y = fmaxf(acc1.y, nrm * v1.y);
            acc1.z = fmaxf(acc1.z, nrm * v1.z); acc1.w = fmaxf(acc1.w, nrm * v1.w);
        } else {
            acc1.x = fmaf(nrm, v1.x, acc1.x); acc1.y = fmaf(nrm, v1.y, acc1.y);
            acc1.z = fmaf(nrm, v1.z, acc1.z); acc1.w = fmaf(nrm, v1.w, acc1.w);
        }
        acc2.x = fmaf(nrm, v2.x, acc2.x); acc2.y = fmaf(nrm, v2.y, acc2.y);
        acc2.z = fmaf(nrm, v2.z, acc2.z); acc2.w = fmaf(nrm, v2.w, acc2.w);
    }

    // combine the 4 groups (same gl across groups -> same slot types)
#pragma unroll
    for (int d = 8; d <= 16; d <<= 1) {
        float t;
        t = __shfl_xor_sync(0xffffffffu, acc0.x, d); acc0.x = fmaxf(acc0.x, t);
        t = __shfl_xor_sync(0xffffffffu, acc0.y, d); acc0.y = fmaxf(acc0.y, t);
        t = __shfl_xor_sync(0xffffffffu, acc0.z, d); acc0.z = fmaxf(acc0.z, t);
        t = __shfl_xor_sync(0xffffffffu, acc0.w, d); acc0.w = fmaxf(acc0.w, t);
        t = __shfl_xor_sync(0xffffffffu, acc1.x, d); acc1.x = m1 ? fmaxf(acc1.x, t) : acc1.x + t;
        t = __shfl_xor_sync(0xffffffffu, acc1.y, d); acc1.y = m1 ? fmaxf(acc1.y, t) : acc1.y + t;
        t = __shfl_xor_sync(0xffffffffu, acc1.z, d); acc1.z = m1 ? fmaxf(acc1.z, t) : acc1.z + t;
        t = __shfl_xor_sync(0xffffffffu, acc1.w, d); acc1.w = m1 ? fmaxf(acc1.w, t) : acc1.w + t;
        t = __shfl_xor_sync(0xffffffffu, acc2.x, d); acc2.x += t;
        t = __shfl_xor_sync(0xffffffffu, acc2.y, d); acc2.y += t;
        t = __shfl_xor_sync(0xffffffffu, acc2.z, d); acc2.z += t;
        t = __shfl_xor_sync(0xffffffffu, acc2.w, d); acc2.w += t;
    }

    float* Yrow = g_Y + (size_t)i * FC;
    if (group == 0) {
        int o0 = gl * 4, o1 = 32 + gl * 4, o2 = 64 + gl * 4;
        float4 y0 = make_float4(fmaxf(acc0.x + sb[o0 + 0], 0.f), fmaxf(acc0.y + sb[o0 + 1], 0.f),
                                fmaxf(acc0.z + sb[o0 + 2], 0.f), fmaxf(acc0.w + sb[o0 + 3], 0.f));
        float4 y1 = make_float4(fmaxf(acc1.x + sb[o1 + 0], 0.f), fmaxf(acc1.y + sb[o1 + 1], 0.f),
                                fmaxf(acc1.z + sb[o1 + 2], 0.f), fmaxf(acc1.w + sb[o1 + 3], 0.f));
        float4 y2 = make_float4(fmaxf(acc2.x + sb[o2 + 0], 0.f), fmaxf(acc2.y + sb[o2 + 1], 0.f),
                                fmaxf(acc2.z + sb[o2 + 2], 0.f), fmaxf(acc2.w + sb[o2 + 3], 0.f));
        *(float4*)(Yrow + o0) = y0;
        *(float4*)(Yrow + o1) = y1;
        *(float4*)(Yrow + o2) = y2;
    }
    if (lane >= 8 && lane < 20) {          // copy hS (already relu(x@WS+bS))
        int o = 96 + (lane - 8) * 4;
        *(float4*)(Yrow + o) = *(const float4*)(Hrow + o);
    }
}

// ---------------- MLP head: out = relu(Y @ W1 + b1) @ W2 + b2 ----------------
__global__ __launch_bounds__(256) void k_mlp(const float* __restrict__ W1, const float* __restrict__ b1,
                                             const float* __restrict__ W2, const float* __restrict__ b2,
                                             float* __restrict__ out) {
    __shared__ float W1s[144 * 64];        // 36 KB, resident whole kernel
    __shared__ float As[16][128];          // A tile, As[k][m]
    __shared__ float b1s[64], W2s[64];
    int tid = threadIdx.x;
    for (int idx = tid; idx < 144 * 64; idx += 256) W1s[idx] = W1[idx];
    if (tid < 64) { b1s[tid] = b1[tid]; W2s[tid] = W2[tid]; }
    __syncthreads();

    int tx = tid & 15, ty = tid >> 4;
    int row0 = blockIdx.x * 128;
    float acc[8][4];
#pragma unroll
    for (int r = 0; r < 8; r++)
#pragma unroll
        for (int c = 0; c < 4; c++) acc[r][c] = 0.f;

    for (int kt = 0; kt < FC; kt += 16) {
#pragma unroll
        for (int l = 0; l < 8; l++) {
            int idx = tid + l * 256;
            int m = idx >> 4, kk = idx & 15;
            int row = row0 + m;
            As[kk][m] = (row < NN) ? g_Y[(size_t)row * FC + kt + kk] : 0.f;
        }
        __syncthreads();
#pragma unroll
        for (int kk = 0; kk < 16; kk++) {
            float a[8], b[4];
#pragma unroll
            for (int r = 0; r < 8; r++) a[r] = As[kk][ty * 8 + r];
#pragma unroll
            for (int c = 0; c < 4; c++) b[c] = W1s[(kt + kk) * 64 + tx * 4 + c];
#pragma unroll
            for (int r = 0; r < 8; r++)
#pragma unroll
                for (int c = 0; c < 4; c++) acc[r][c] = fmaf(a[r], b[c], acc[r][c]);
        }
        __syncthreads();
    }

    float part[8];
#pragma unroll
    for (int r = 0; r < 8; r++) {
        float p = 0.f;
#pragma unroll
        for (int c = 0; c < 4; c++) {
            float t = fmaxf(acc[r][c] + b1s[tx * 4 + c], 0.f);
            p = fmaf(t, W2s[tx * 4 + c], p);
        }
        part[r] = p;
    }
#pragma unroll
    for (int d = 1; d < 16; d <<= 1)
#pragma unroll
        for (int r = 0; r < 8; r++) part[r] += __shfl_xor_sync(0xffffffffu, part[r], d);

    if (tx == 0) {
        float bb = b2[0];
#pragma unroll
        for (int r = 0; r < 8; r++) {
            int row = row0 + ty * 8 + r;
            if (row < NN) out[row] = part[r] + bb;
        }
    }
}

// ---------------- launch ----------------
extern "C" void kernel_launch(void* const* d_in, const int* in_sizes, int n_in,
                              void* d_out, int out_size) {
    const float* x  = (const float*)d_in[0];
    const int*   ei = (const int*)d_in[1];       // int32 OR int64 (detected on device)
    const float* ew = (const float*)d_in[2];
    const float* WM = (const float*)d_in[3];
    const float* bM = (const float*)d_in[4];
    const float* WA = (const float*)d_in[5];
    const float* bA = (const float*)d_in[6];
    const float* WS = (const float*)d_in[7];
    const float* bS = (const float*)d_in[8];
    const float* W1 = (const float*)d_in[9];
    const float* b1 = (const float*)d_in[10];
    const float* W2 = (const float*)d_in[11];
    const float* b2 = (const float*)d_in[12];
    float* out = (float*)d_out;

    k_detect<<<1, 32>>>(ei);
    k_init<<<(NN + 255) / 256, 256>>>();
    k_edges<<<(NE + 255) / 256, 256>>>(ei, ew);
    k_dis<<<(NN + 255) / 256, 256>>>();
    k_scan<<<1, 1024>>>();
    k_pack<<<(FIN * FC + 255) / 256, 256>>>(WM, WA, WS, bS);
    k_gemm1<<<(NN + 127) / 128, 256>>>(x);
    k_csr<<<(NE + 255) / 256, 256>>>(ew);
    k_agg<<<NN / 8, 256>>>(bM, bA);
    k_mlp<<<(NN + 127) / 128, 256>>>(W1, b1, W2, b2, out);
}

// round 3
// speedup vs baseline: 1.0885x; 1.0885x over previous
#include <cuda_runtime.h>
#include <math_constants.h>

#define NN 50000
#define NE 1600000
#define FIN 264
#define FH 48
#define FC 144
#define FM 64

typedef unsigned long long u64;
typedef unsigned int u32;

// ---------------- scratch (static __device__ globals; no allocs) ----------------
__device__ int   g_is64;
__device__ int   g_row[NE];
__device__ int   g_col[NE];
__device__ float g_deg[NN];                 // degree, then dis (in-place rsqrt)
__device__ int   g_count[NN];
__device__ int   g_off[NN + 1];
__device__ int   g_cursor[NN];
__device__ int2  g_csr[NE];                 // per sorted edge: (src row, norm bits)
__device__ float g_H[(size_t)NN * FC];      // [hM | hA | hS(relu+bias)] per node
__device__ float g_Y[(size_t)NN * FC];      // concat features for MLP

// packed f32x2 FMA (Blackwell FFMA2 — only reachable via PTX)
__device__ __forceinline__ void ffma2(u64& d, u64 a, u64 b) {
    asm("fma.rn.f32x2 %0, %1, %2, %0;" : "+l"(d) : "l"(a), "l"(b));
}
__device__ __forceinline__ u64 dup2(float v) {
    u32 u = __float_as_uint(v);
    return (u64)u | ((u64)u << 32);
}
__device__ __forceinline__ float lo2(u64 v) { return __uint_as_float((u32)v); }
__device__ __forceinline__ float hi2(u64 v) { return __uint_as_float((u32)(v >> 32)); }

// ---------------- init (+ edge dtype detect on thread 0) ----------------
__global__ void k_init(const int* __restrict__ ei32) {
    int i = blockIdx.x * blockDim.x + threadIdx.x;
    if (i < NN) { g_deg[i] = 1.0f; g_count[i] = 0; }
    if (i == 0) {
        int all0 = 1;
        for (int k = 0; k < 32; k++)
            if (ei32[2 * k + 1] != 0) { all0 = 0; break; }
        g_is64 = all0;   // int64 LE with values<2^31 -> odd words all zero
    }
}

// ---------------- extract edges (dtype-agnostic) + degree/in-degree histogram ----------------
__global__ void k_edges(const int* __restrict__ ei32, const float* __restrict__ ew) {
    int e = blockIdx.x * blockDim.x + threadIdx.x;
    if (e < NE) {
        int row, col;
        if (g_is64) {
            row = ei32[2 * e];
            col = ei32[2 * (NE + e)];
        } else {
            row = ei32[e];
            col = ei32[NE + e];
        }
        g_row[e] = row;
        g_col[e] = col;
        atomicAdd(&g_deg[col], ew[e]);
        atomicAdd(&g_count[col], 1);
    }
}

// ---------------- fused: dis = rsqrt(deg), 3-phase exclusive scan of counts ----------------
__global__ void k_scan() {
    __shared__ int s[1024];
    int tid = threadIdx.x;
    for (int i = tid; i < NN; i += 1024)
        g_deg[i] = rsqrtf(g_deg[i]);     // deg >= 1 always (self loop weight 1)

    const int CH = (NN + 1023) / 1024;   // 49
    int lo = tid * CH;
    int hi = lo + CH; if (hi > NN) hi = NN;
    int sum = 0;
    for (int i = lo; i < hi; i++) sum += g_count[i];
    s[tid] = sum;
    __syncthreads();
    for (int off = 1; off < 1024; off <<= 1) {
        int t = (tid >= off) ? s[tid - off] : 0;
        __syncthreads();
        s[tid] += t;
        __syncthreads();
    }
    int run = s[tid] - sum;              // exclusive prefix of this thread's chunk
    for (int i = lo; i < hi; i++) {
        g_off[i] = run; g_cursor[i] = run;
        run += g_count[i];
    }
    if (tid == 1023) g_off[NN] = run;    // == NE
}

// ---------------- GEMM1: H = x @ [WM|WA|WS]  (cols>=96: +bS, relu)  — FFMA2 ----------------
__global__ __launch_bounds__(256) void k_gemm1(const float* __restrict__ x,
                                               const float* __restrict__ WM,
                                               const float* __restrict__ WA,
                                               const float* __restrict__ WS,
                                               const float* __restrict__ bS) {
    __shared__ float As[8][132];         // padded: conflict-free 4-way STS
    __shared__ u64   Bs2[8][144];        // weights pre-duplicated (v,v)
    int tid = threadIdx.x;
    int tx = tid & 15, ty = tid >> 4;
    int row0 = blockIdx.x * 128;

    u64 acc[4][9];
#pragma unroll
    for (int r = 0; r < 4; r++)
#pragma unroll
        for (int c = 0; c < 9; c++) acc[r][c] = 0ull;

    for (int kt = 0; kt < FIN; kt += 8) {
        {   // A tile: 128 rows x 8 k, float4 per thread
            int m = tid >> 1;
            int kb = (tid & 1) * 4;
            int row = row0 + m;
            float4 v = make_float4(0.f, 0.f, 0.f, 0.f);
            if (row < NN) v = *(const float4*)&x[(size_t)row * FIN + kt + kb];
            As[kb + 0][m] = v.x; As[kb + 1][m] = v.y;
            As[kb + 2][m] = v.z; As[kb + 3][m] = v.w;
        }
        for (int idx = tid; idx < 8 * 144; idx += 256) {
            int kk = idx / 144, c = idx - kk * 144;
            int k = kt + kk;
            float v = (c < 48) ? WM[k * FH + c]
                    : (c < 96) ? WA[k * FH + (c - 48)]
                               : WS[k * FH + (c - 96)];
            Bs2[kk][c] = dup2(v);
        }
        __syncthreads();
#pragma unroll
        for (int kk = 0; kk < 8; kk++) {
            u64 aa[4], bb[9];
#pragma unroll
            for (int r = 0; r < 4; r++)
                aa[r] = *(const u64*)&As[kk][ty * 8 + r * 2];
#pragma unroll
            for (int c = 0; c < 9; c++) bb[c] = Bs2[kk][tx * 9 + c];
#pragma unroll
            for (int r = 0; r < 4; r++)
#pragma unroll
                for (int c = 0; c < 9; c++) ffma2(acc[r][c], aa[r], bb[c]);
        }
        __syncthreads();
    }
#pragma unroll
    for (int r = 0; r < 4; r++) {
        int r0 = row0 + ty * 8 + r * 2;
#pragma unroll
        for (int c = 0; c < 9; c++) {
            int col = tx * 9 + c;
            float vl = lo2(acc[r][c]), vh = hi2(acc[r][c]);
            if (col >= 96) {
                float b = bS[col - 96];
                vl = fmaxf(vl + b, 0.f);
                vh = fmaxf(vh + b, 0.f);
            }
            if (r0 < NN)     g_H[(size_t)r0 * FC + col]       = vl;
            if (r0 + 1 < NN) g_H[(size_t)(r0 + 1) * FC + col] = vh;
        }
    }
}

// ---------------- CSR scatter: group edges by destination col ----------------
__global__ void k_csr(const float* __restrict__ ew) {
    int e = blockIdx.x * blockDim.x + threadIdx.x;
    if (e < NE) {
        int row = g_row[e];
        int col = g_col[e];
        float nrm = g_deg[row] * ew[e] * g_deg[col];   // g_deg holds dis now
        int pos = atomicAdd(&g_cursor[col], 1);
        g_csr[pos] = make_int2(row, __float_as_int(nrm));
    }
}

// ---------------- aggregation: 1 warp per node, 8 lanes per edge, no atomics ----------------
__global__ __launch_bounds__(256) void k_agg(const float* __restrict__ bM, const float* __restrict__ bA) {
    __shared__ float sb[96];
    int tid = threadIdx.x;
    if (tid < 96) sb[tid] = (tid < 48) ? bM[tid] : bA[tid - 48];
    __syncthreads();

    int wid = tid >> 5;
    int i = blockIdx.x * 8 + wid;          // grid = NN/8 exactly
    int lane = tid & 31;
    int group = lane >> 3;
    int gl = lane & 7;
    bool m1 = (gl < 4);                    // slot1: max for gl<4, add otherwise
    const float NINF = -CUDART_INF_F;

    const float* Hrow = g_H + (size_t)i * FC;
    float4 acc0, acc1, acc2;
    if (group == 0) {
        float dii = g_deg[i];
        float sm = dii * dii;              // self-loop norm
        float4 v0 = *(const float4*)(Hrow + gl * 4);
        float4 v1 = *(const float4*)(Hrow + 32 + gl * 4);
        float4 v2 = *(const float4*)(Hrow + 64 + gl * 4);
        acc0 = make_float4(sm * v0.x, sm * v0.y, sm * v0.z, sm * v0.w);
        acc1 = make_float4(sm * v1.x, sm * v1.y, sm * v1.z, sm * v1.w);
        acc2 = make_float4(sm * v2.x, sm * v2.y, sm * v2.z, sm * v2.w);
    } else {
        acc0 = make_float4(NINF, NINF, NINF, NINF);
        float i1 = m1 ? NINF : 0.f;
        acc1 = make_float4(i1, i1, i1, i1);
        acc2 = make_float4(0.f, 0.f, 0.f, 0.f);
    }

    int s0 = g_off[i], s1 = g_off[i + 1];
    for (int j = s0 + group; j < s1; j += 4) {
        int2 p = g_csr[j];
        const float* Hr = g_H + (size_t)p.x * FC;
        float nrm = __int_as_float(p.y);
        float4 v0 = *(const float4*)(Hr + gl * 4);
        float4 v1 = *(const float4*)(Hr + 32 + gl * 4);
        float4 v2 = *(const float4*)(Hr + 64 + gl * 4);
        acc0.x = fmaxf(acc0.x, nrm * v0.x); acc0.y = fmaxf(acc0.y, nrm * v0.y);
        acc0.z = fmaxf(acc0.z, nrm * v0.z); acc0.w = fmaxf(acc0.w, nrm * v0.w);
        if (m1) {
            acc1.x = fmaxf(acc1.x, nrm * v1.x); acc1.y = fmaxf(acc1.y, nrm * v1.y);
            acc1.z = fmaxf(acc1.z, nrm * v1.z); acc1.w = fmaxf(acc1.w, nrm * v1.w);
        } else {
            acc1.x = fmaf(nrm, v1.x, acc1.x); acc1.y = fmaf(nrm, v1.y, acc1.y);
            acc1.z = fmaf(nrm, v1.z, acc1.z); acc1.w = fmaf(nrm, v1.w, acc1.w);
        }
        acc2.x = fmaf(nrm, v2.x, acc2.x); acc2.y = fmaf(nrm, v2.y, acc2.y);
        acc2.z = fmaf(nrm, v2.z, acc2.z); acc2.w = fmaf(nrm, v2.w, acc2.w);
    }

    // combine the 4 groups (same gl across groups -> same slot types)
#pragma unroll
    for (int d = 8; d <= 16; d <<= 1) {
        float t;
        t = __shfl_xor_sync(0xffffffffu, acc0.x, d); acc0.x = fmaxf(acc0.x, t);
        t = __shfl_xor_sync(0xffffffffu, acc0.y, d); acc0.y = fmaxf(acc0.y, t);
        t = __shfl_xor_sync(0xffffffffu, acc0.z, d); acc0.z = fmaxf(acc0.z, t);
        t = __shfl_xor_sync(0xffffffffu, acc0.w, d); acc0.w = fmaxf(acc0.w, t);
        t = __shfl_xor_sync(0xffffffffu, acc1.x, d); acc1.x = m1 ? fmaxf(acc1.x, t) : acc1.x + t;
        t = __shfl_xor_sync(0xffffffffu, acc1.y, d); acc1.y = m1 ? fmaxf(acc1.y, t) : acc1.y + t;
        t = __shfl_xor_sync(0xffffffffu, acc1.z, d); acc1.z = m1 ? fmaxf(acc1.z, t) : acc1.z + t;
        t = __shfl_xor_sync(0xffffffffu, acc1.w, d); acc1.w = m1 ? fmaxf(acc1.w, t) : acc1.w + t;
        t = __shfl_xor_sync(0xffffffffu, acc2.x, d); acc2.x += t;
        t = __shfl_xor_sync(0xffffffffu, acc2.y, d); acc2.y += t;
        t = __shfl_xor_sync(0xffffffffu, acc2.z, d); acc2.z += t;
        t = __shfl_xor_sync(0xffffffffu, acc2.w, d); acc2.w += t;
    }

    float* Yrow = g_Y + (size_t)i * FC;
    if (group == 0) {
        int o0 = gl * 4, o1 = 32 + gl * 4, o2 = 64 + gl * 4;
        float4 y0 = make_float4(fmaxf(acc0.x + sb[o0 + 0], 0.f), fmaxf(acc0.y + sb[o0 + 1], 0.f),
                                fmaxf(acc0.z + sb[o0 + 2], 0.f), fmaxf(acc0.w + sb[o0 + 3], 0.f));
        float4 y1 = make_float4(fmaxf(acc1.x + sb[o1 + 0], 0.f), fmaxf(acc1.y + sb[o1 + 1], 0.f),
                                fmaxf(acc1.z + sb[o1 + 2], 0.f), fmaxf(acc1.w + sb[o1 + 3], 0.f));
        float4 y2 = make_float4(fmaxf(acc2.x + sb[o2 + 0], 0.f), fmaxf(acc2.y + sb[o2 + 1], 0.f),
                                fmaxf(acc2.z + sb[o2 + 2], 0.f), fmaxf(acc2.w + sb[o2 + 3], 0.f));
        *(float4*)(Yrow + o0) = y0;
        *(float4*)(Yrow + o1) = y1;
        *(float4*)(Yrow + o2) = y2;
    }
    if (lane >= 8 && lane < 20) {          // copy hS (already relu(x@WS+bS))
        int o = 96 + (lane - 8) * 4;
        *(float4*)(Yrow + o) = *(const float4*)(Hrow + o);
    }
}

// ---------------- MLP head: out = relu(Y @ W1 + b1) @ W2 + b2  — FFMA2 (col pairs) ----------------
__global__ __launch_bounds__(256) void k_mlp(const float* __restrict__ W1, const float* __restrict__ b1,
                                             const float* __restrict__ W2, const float* __restrict__ b2,
                                             float* __restrict__ out) {
    __shared__ float W1s[FC * FM];         // 36 KB, resident whole kernel
    __shared__ float As[16][132];
    __shared__ float b1s[FM], W2s[FM];
    int tid = threadIdx.x;
    for (int idx = tid; idx < FC * FM; idx += 256) W1s[idx] = W1[idx];
    if (tid < FM) { b1s[tid] = b1[tid]; W2s[tid] = W2[tid]; }
    __syncthreads();

    int tx = tid & 15, ty = tid >> 4;
    int row0 = blockIdx.x * 128;
    u64 acc[8][2];
#pragma unroll
    for (int r = 0; r < 8; r++) { acc[r][0] = 0ull; acc[r][1] = 0ull; }

    for (int kt = 0; kt < FC; kt += 16) {
        {   // A tile: 128 rows x 16 k; each thread 8 floats = 2x float4
            int m = tid >> 1;
            int kb = (tid & 1) * 8;
            int row = row0 + m;
            float4 v0 = make_float4(0.f, 0.f, 0.f, 0.f), v1 = v0;
            if (row < NN) {
                v0 = *(const float4*)&g_Y[(size_t)row * FC + kt + kb];
                v1 = *(const float4*)&g_Y[(size_t)row * FC + kt + kb + 4];
            }
            As[kb + 0][m] = v0.x; As[kb + 1][m] = v0.y; As[kb + 2][m] = v0.z; As[kb + 3][m] = v0.w;
            As[kb + 4][m] = v1.x; As[kb + 5][m] = v1.y; As[kb + 6][m] = v1.z; As[kb + 7][m] = v1.w;
        }
        __syncthreads();
#pragma unroll
        for (int kk = 0; kk < 16; kk++) {
            u64 bb0 = *(const u64*)&W1s[(kt + kk) * FM + tx * 4];
            u64 bb1 = *(const u64*)&W1s[(kt + kk) * FM + tx * 4 + 2];
#pragma unroll
            for (int r = 0; r < 8; r++) {
                u64 aa = dup2(As[kk][ty * 8 + r]);
                ffma2(acc[r][0], aa, bb0);
                ffma2(acc[r][1], aa, bb1);
            }
        }
        __syncthreads();
    }

    float part[8];
    int c0 = tx * 4;
#pragma unroll
    for (int r = 0; r < 8; r++) {
        float t0 = fmaxf(lo2(acc[r][0]) + b1s[c0 + 0], 0.f);
        float t1 = fmaxf(hi2(acc[r][0]) + b1s[c0 + 1], 0.f);
        float t2 = fmaxf(lo2(acc[r][1]) + b1s[c0 + 2], 0.f);
        float t3 = fmaxf(hi2(acc[r][1]) + b1s[c0 + 3], 0.f);
        part[r] = t0 * W2s[c0] + t1 * W2s[c0 + 1] + t2 * W2s[c0 + 2] + t3 * W2s[c0 + 3];
    }
#pragma unroll
    for (int d = 1; d < 16; d <<= 1)
#pragma unroll
        for (int r = 0; r < 8; r++) part[r] += __shfl_xor_sync(0xffffffffu, part[r], d);

    if (tx == 0) {
        float bb = b2[0];
#pragma unroll
        for (int r = 0; r < 8; r++) {
            int row = row0 + ty * 8 + r;
            if (row < NN) out[row] = part[r] + bb;
        }
    }
}

// ---------------- launch ----------------
extern "C" void kernel_launch(void* const* d_in, const int* in_sizes, int n_in,
                              void* d_out, int out_size) {
    const float* x  = (const float*)d_in[0];
    const int*   ei = (const int*)d_in[1];       // int32 OR int64 (detected on device)
    const float* ew = (const float*)d_in[2];
    const float* WM = (const float*)d_in[3];
    const float* bM = (const float*)d_in[4];
    const float* WA = (const float*)d_in[5];
    const float* bA = (const float*)d_in[6];
    const float* WS = (const float*)d_in[7];
    const float* bS = (const float*)d_in[8];
    const float* W1 = (const float*)d_in[9];
    const float* b1 = (const float*)d_in[10];
    const float* W2 = (const float*)d_in[11];
    const float* b2 = (const float*)d_in[12];
    float* out = (float*)d_out;

    k_init<<<(NN + 255) / 256, 256>>>(ei);
    k_edges<<<(NE + 255) / 256, 256>>>(ei, ew);
    k_scan<<<1, 1024>>>();
    k_gemm1<<<(NN + 127) / 128, 256>>>(x, WM, WA, WS, bS);
    k_csr<<<(NE + 255) / 256, 256>>>(ew);
    k_agg<<<NN / 8, 256>>>(bM, bA);
    k_mlp<<<(NN + 127) / 128, 256>>>(W1, b1, W2, b2, out);
}

// round 5
// speedup vs baseline: 1.3968x; 1.2832x over previous
#include <cuda_runtime.h>
#include <math_constants.h>
#include <cstdint>

#define NN 50000
#define NE 1600000
#define FIN 264
#define FH 48
#define FC 144
#define FM 64
#define KPAD 272                      // 264 padded to 17 chunks of 16
#define NPAD 50048                    // 50000 padded to 391*128
#define CK 16
#define NCH 17

typedef unsigned long long u64;
typedef unsigned int u32;

// ---------------- scratch (static __device__ globals; no allocs) ----------------
__device__ int   g_is64;
__device__ int   g_row[NE];
__device__ int   g_col[NE];
__device__ float g_deg[NN];
__device__ int   g_count[NN];
__device__ int   g_off[NN + 1];
__device__ int   g_cursor[NN];
__device__ int2  g_csr[NE];
__device__ float g_H[(size_t)NN * FC];
__device__ float g_Y[(size_t)NN * FC];
__device__ float g_xT[(size_t)KPAD * NPAD];   // x transposed [k][row], zero-padded
__device__ float g_Wd[KPAD * FC];             // [WM|WA|WS] k-major, zero-padded

// ---------------- helpers ----------------
__device__ __forceinline__ void ffma2(u64& d, u64 a, u64 b) {
    asm("fma.rn.f32x2 %0, %1, %2, %0;" : "+l"(d) : "l"(a), "l"(b));
}
__device__ __forceinline__ u64 dup2(float v) {
    u32 u = __float_as_uint(v);
    return (u64)u | ((u64)u << 32);
}
__device__ __forceinline__ float lo2(u64 v) { return __uint_as_float((u32)v); }
__device__ __forceinline__ float hi2(u64 v) { return __uint_as_float((u32)(v >> 32)); }
__device__ __forceinline__ u32 smem_u32(const void* p) {
    u32 a;
    asm("{ .reg .u64 t; cvta.to.shared.u64 t, %1; cvt.u32.u64 %0, t; }" : "=r"(a) : "l"(p));
    return a;
}
__device__ __forceinline__ void cpa16(u32 dst, const float* src) {
    asm volatile("cp.async.cg.shared.global [%0], [%1], 16;" :: "r"(dst), "l"(src));
}
#define CPA_COMMIT() asm volatile("cp.async.commit_group;" ::: "memory")
#define CPA_WAIT1()  asm volatile("cp.async.wait_group 1;" ::: "memory")
#define CPA_WAIT0()  asm volatile("cp.async.wait_group 0;" ::: "memory")

// ---------------- init (+ edge dtype detect on thread 0) ----------------
__global__ void k_init(const int* __restrict__ ei32) {
    int i = blockIdx.x * blockDim.x + threadIdx.x;
    if (i < NN) { g_deg[i] = 1.0f; g_count[i] = 0; }
    if (i == 0) {
        int all0 = 1;
        for (int k = 0; k < 32; k++)
            if (ei32[2 * k + 1] != 0) { all0 = 0; break; }
        g_is64 = all0;   // int64 LE with values<2^31 -> odd words all zero
    }
}

// ---------------- extract edges + degree/in-degree histogram ----------------
__global__ void k_edges(const int* __restrict__ ei32, const float* __restrict__ ew) {
    int e = blockIdx.x * blockDim.x + threadIdx.x;
    if (e < NE) {
        int row, col;
        if (g_is64) { row = ei32[2 * e]; col = ei32[2 * (NE + e)]; }
        else        { row = ei32[e];     col = ei32[NE + e]; }
        g_row[e] = row;
        g_col[e] = col;
        atomicAdd(&g_deg[col], ew[e]);
        atomicAdd(&g_count[col], 1);
    }
}

// ---------------- fused: dis = rsqrt(deg), 3-phase exclusive scan of counts ----------------
__global__ void k_scan() {
    __shared__ int s[1024];
    int tid = threadIdx.x;
    for (int i = tid; i < NN; i += 1024)
        g_deg[i] = rsqrtf(g_deg[i]);

    const int CH = (NN + 1023) / 1024;
    int lo = tid * CH;
    int hi = lo + CH; if (hi > NN) hi = NN;
    int sum = 0;
    for (int i = lo; i < hi; i++) sum += g_count[i];
    s[tid] = sum;
    __syncthreads();
    for (int off = 1; off < 1024; off <<= 1) {
        int t = (tid >= off) ? s[tid - off] : 0;
        __syncthreads();
        s[tid] += t;
        __syncthreads();
    }
    int run = s[tid] - sum;
    for (int i = lo; i < hi; i++) {
        g_off[i] = run; g_cursor[i] = run;
        run += g_count[i];
    }
    if (tid == 1023) g_off[NN] = run;
}

// ---------------- transpose x -> g_xT [272][50048], zero-padded ----------------
__global__ __launch_bounds__(256) void k_xT(const float* __restrict__ x) {
    __shared__ float t[32][33];
    int tx = threadIdx.x & 31, ty = threadIdx.x >> 5;   // 32 x 8
    int r0 = blockIdx.x * 32;                           // grid.x = 1564
    int k0 = blockIdx.y * 32;                           // grid.y = 9
#pragma unroll
    for (int i = 0; i < 4; i++) {
        int row = r0 + ty + i * 8;
        int k = k0 + tx;
        t[ty + i * 8][tx] = (row < NN && k < FIN) ? x[(size_t)row * FIN + k] : 0.f;
    }
    __syncthreads();
#pragma unroll
    for (int i = 0; i < 4; i++) {
        int k = k0 + ty + i * 8;
        int row = r0 + tx;
        if (k < KPAD) g_xT[(size_t)k * NPAD + row] = t[tx][ty + i * 8];
    }
}

// ---------------- pack weights k-major, zero-padded ----------------
__global__ void k_pack(const float* __restrict__ WM, const float* __restrict__ WA,
                       const float* __restrict__ WS) {
    int idx = blockIdx.x * blockDim.x + threadIdx.x;
    if (idx < KPAD * FC) {
        int k = idx / FC, c = idx - (idx / FC) * FC;
        float v = 0.f;
        if (k < FIN)
            v = (c < 48) ? WM[k * FH + c] : (c < 96) ? WA[k * FH + c - 48] : WS[k * FH + c - 96];
        g_Wd[idx] = v;
    }
}

// ---------------- GEMM1: H = x @ [WM|WA|WS], cp.async double-buffered, FFMA2 ----------------
__global__ __launch_bounds__(256) void k_gemm1(const float* __restrict__ bS) {
    __shared__ float As[2][CK][128];     // 16 KB
    __shared__ float Bs[2][CK][FC];      // 18 KB
    int tid = threadIdx.x;
    int tx = tid & 15, ty = tid >> 4;
    int row0 = blockIdx.x * 128;

    u32 asb[2], bsb[2];
    asb[0] = smem_u32(&As[0][0][0]); asb[1] = smem_u32(&As[1][0][0]);
    bsb[0] = smem_u32(&Bs[0][0][0]); bsb[1] = smem_u32(&Bs[1][0][0]);

    // issue loads for chunk ch into buffer s
    auto load_chunk = [&](int ch, int s) {
        int kt = ch * CK;
        // A: 16x128 floats = 512 x 16B
#pragma unroll
        for (int l = 0; l < 2; l++) {
            int idx = tid + l * 256;
            int kk = idx >> 5, m4 = idx & 31;
            cpa16(asb[s] + (u32)(kk * 128 + m4 * 4) * 4,
                  &g_xT[(size_t)(kt + kk) * NPAD + row0 + m4 * 4]);
        }
        // B: 16x144 floats = 576 x 16B
#pragma unroll
        for (int l = 0; l < 3; l++) {
            int idx = tid + l * 256;
            if (idx < 576) {
                int kk = idx / 36, c4 = idx - (idx / 36) * 36;
                cpa16(bsb[s] + (u32)(kk * FC + c4 * 4) * 4,
                      &g_Wd[(kt + kk) * FC + c4 * 4]);
            }
        }
        CPA_COMMIT();
    };

    u64 acc[4][9];
#pragma unroll
    for (int r = 0; r < 4; r++)
#pragma unroll
        for (int c = 0; c < 9; c++) acc[r][c] = 0ull;

    load_chunk(0, 0);
    load_chunk(1, 1);

    for (int ch = 0; ch < NCH; ch++) {
        int s = ch & 1;
        if (ch < NCH - 1) CPA_WAIT1(); else CPA_WAIT0();
        __syncthreads();                 // chunk ch visible to all; all warps done with buf s
        // compute chunk ch
#pragma unroll
        for (int kk = 0; kk < CK; kk++) {
            u64 aa[4], bb[9];
#pragma unroll
            for (int r = 0; r < 4; r++)
                aa[r] = *(const u64*)&As[s][kk][ty * 8 + r * 2];
#pragma unroll
            for (int c = 0; c < 9; c++) bb[c] = dup2(Bs[s][kk][tx * 9 + c]);
#pragma unroll
            for (int r = 0; r < 4; r++)
#pragma unroll
                for (int c = 0; c < 9; c++) ffma2(acc[r][c], aa[r], bb[c]);
        }
        __syncthreads();                 // all warps done reading buf s
        if (ch + 2 < NCH) load_chunk(ch + 2, s);
    }

    // epilogue
#pragma unroll
    for (int r = 0; r < 4; r++) {
        int r0g = row0 + ty * 8 + r * 2;
#pragma unroll
        for (int c = 0; c < 9; c++) {
            int col = tx * 9 + c;
            float vl = lo2(acc[r][c]), vh = hi2(acc[r][c]);
            if (col >= 96) {
                float b = bS[col - 96];
                vl = fmaxf(vl + b, 0.f);
                vh = fmaxf(vh + b, 0.f);
            }
            if (r0g < NN)     g_H[(size_t)r0g * FC + col]       = vl;
            if (r0g + 1 < NN) g_H[(size_t)(r0g + 1) * FC + col] = vh;
        }
    }
}

// ---------------- CSR scatter: group edges by destination col ----------------
__global__ void k_csr(const float* __restrict__ ew) {
    int e = blockIdx.x * blockDim.x + threadIdx.x;
    if (e < NE) {
        int row = g_row[e];
        int col = g_col[e];
        float nrm = g_deg[row] * ew[e] * g_deg[col];
        int pos = atomicAdd(&g_cursor[col], 1);
        g_csr[pos] = make_int2(row, __float_as_int(nrm));
    }
}

// ---------------- aggregation: 1 warp per node, 8 lanes per edge, no atomics ----------------
__global__ __launch_bounds__(256) void k_agg(const float* __restrict__ bM, const float* __restrict__ bA) {
    __shared__ float sb[96];
    int tid = threadIdx.x;
    if (tid < 96) sb[tid] = (tid < 48) ? bM[tid] : bA[tid - 48];
    __syncthreads();

    int wid = tid >> 5;
    int i = blockIdx.x * 8 + wid;
    int lane = tid & 31;
    int group = lane >> 3;
    int gl = lane & 7;
    bool m1 = (gl < 4);
    const float NINF = -CUDART_INF_F;

    const float* Hrow = g_H + (size_t)i * FC;
    float4 acc0, acc1, acc2;
    if (group == 0) {
        float dii = g_deg[i];
        float sm = dii * dii;
        float4 v0 = *(const float4*)(Hrow + gl * 4);
        float4 v1 = *(const float4*)(Hrow + 32 + gl * 4);
        float4 v2 = *(const float4*)(Hrow + 64 + gl * 4);
        acc0 = make_float4(sm * v0.x, sm * v0.y, sm * v0.z, sm * v0.w);
        acc1 = make_float4(sm * v1.x, sm * v1.y, sm * v1.z, sm * v1.w);
        acc2 = make_float4(sm * v2.x, sm * v2.y, sm * v2.z, sm * v2.w);
    } else {
        acc0 = make_float4(NINF, NINF, NINF, NINF);
        float i1 = m1 ? NINF : 0.f;
        acc1 = make_float4(i1, i1, i1, i1);
        acc2 = make_float4(0.f, 0.f, 0.f, 0.f);
    }

    int s0 = g_off[i], s1 = g_off[i + 1];
    for (int j = s0 + group; j < s1; j += 4) {
        int2 p = g_csr[j];
        const float* Hr = g_H + (size_t)p.x * FC;
        float nrm = __int_as_float(p.y);
        float4 v0 = *(const float4*)(Hr + gl * 4);
        float4 v1 = *(const float4*)(Hr + 32 + gl * 4);
        float4 v2 = *(const float4*)(Hr + 64 + gl * 4);
        acc0.x = fmaxf(acc0.x, nrm * v0.x); acc0.y = fmaxf(acc0.y, nrm * v0.y);
        acc0.z = fmaxf(acc0.z, nrm * v0.z); acc0.w = fmaxf(acc0.w, nrm * v0.w);
        if (m1) {
            acc1.x = fmaxf(acc1.x, nrm * v1.x); acc1.y = fmaxf(acc1.y, nrm * v1.y);
            acc1.z = fmaxf(acc1.z, nrm * v1.z); acc1.w = fmaxf(acc1.w, nrm * v1.w);
        } else {
            acc1.x = fmaf(nrm, v1.x, acc1.x); acc1.y = fmaf(nrm, v1.y, acc1.y);
            acc1.z = fmaf(nrm, v1.z, acc1.z); acc1.w = fmaf(nrm, v1.w, acc1.w);
        }
        acc2.x = fmaf(nrm, v2.x, acc2.x); acc2.y = fmaf(nrm, v2.y, acc2.y);
        acc2.z = fmaf(nrm, v2.z, acc2.z); acc2.w = fmaf(nrm, v2.w, acc2.w);
    }

#pragma unroll
    for (int d = 8; d <= 16; d <<= 1) {
        float t;
        t = __shfl_xor_sync(0xffffffffu, acc0.x, d); acc0.x = fmaxf(acc0.x, t);
        t = __shfl_xor_sync(0xffffffffu, acc0.y, d); acc0.y = fmaxf(acc0.y, t);
        t = __shfl_xor_sync(0xffffffffu, acc0.z, d); acc0.z = fmaxf(acc0.z, t);
        t = __shfl_xor_sync(0xffffffffu, acc0.w, d); acc0.w = fmaxf(acc0.w, t);
        t = __shfl_xor_sync(0xffffffffu, acc1.x, d); acc1.x = m1 ? fmaxf(acc1.x, t) : acc1.x + t;
        t = __shfl_xor_sync(0xffffffffu, acc1.y, d); acc1.y = m1 ? fmaxf(acc1.y, t) : acc1.y + t;
        t = __shfl_xor_sync(0xffffffffu, acc1.z, d); acc1.z = m1 ? fmaxf(acc1.z, t) : acc1.z + t;
        t = __shfl_xor_sync(0xffffffffu, acc1.w, d); acc1.w = m1 ? fmaxf(acc1.w, t) : acc1.w + t;
        t = __shfl_xor_sync(0xffffffffu, acc2.x, d); acc2.x += t;
        t = __shfl_xor_sync(0xffffffffu, acc2.y, d); acc2.y += t;
        t = __shfl_xor_sync(0xffffffffu, acc2.z, d); acc2.z += t;
        t = __shfl_xor_sync(0xffffffffu, acc2.w, d); acc2.w += t;
    }

    float* Yrow = g_Y + (size_t)i * FC;
    if (group == 0) {
        int o0 = gl * 4, o1 = 32 + gl * 4, o2 = 64 + gl * 4;
        float4 y0 = make_float4(fmaxf(acc0.x + sb[o0 + 0], 0.f), fmaxf(acc0.y + sb[o0 + 1], 0.f),
                                fmaxf(acc0.z + sb[o0 + 2], 0.f), fmaxf(acc0.w + sb[o0 + 3], 0.f));
        float4 y1 = make_float4(fmaxf(acc1.x + sb[o1 + 0], 0.f), fmaxf(acc1.y + sb[o1 + 1], 0.f),
                                fmaxf(acc1.z + sb[o1 + 2], 0.f), fmaxf(acc1.w + sb[o1 + 3], 0.f));
        float4 y2 = make_float4(fmaxf(acc2.x + sb[o2 + 0], 0.f), fmaxf(acc2.y + sb[o2 + 1], 0.f),
                                fmaxf(acc2.z + sb[o2 + 2], 0.f), fmaxf(acc2.w + sb[o2 + 3], 0.f));
        *(float4*)(Yrow + o0) = y0;
        *(float4*)(Yrow + o1) = y1;
        *(float4*)(Yrow + o2) = y2;
    }
    if (lane >= 8 && lane < 20) {
        int o = 96 + (lane - 8) * 4;
        *(float4*)(Yrow + o) = *(const float4*)(Hrow + o);
    }
}

// ---------------- MLP head: out = relu(Y @ W1 + b1) @ W2 + b2  — FFMA2 ----------------
__global__ __launch_bounds__(256) void k_mlp(const float* __restrict__ W1, const float* __restrict__ b1,
                                             const float* __restrict__ W2, const float* __restrict__ b2,
                                             float* __restrict__ out) {
    __shared__ float W1s[FC * FM];
    __shared__ float As[16][132];
    __shared__ float b1s[FM], W2s[FM];
    int tid = threadIdx.x;
    for (int idx = tid; idx < FC * FM; idx += 256) W1s[idx] = W1[idx];
    if (tid < FM) { b1s[tid] = b1[tid]; W2s[tid] = W2[tid]; }
    __syncthreads();

    int tx = tid & 15, ty = tid >> 4;
    int row0 = blockIdx.x * 128;
    u64 acc[8][2];
#pragma unroll
    for (int r = 0; r < 8; r++) { acc[r][0] = 0ull; acc[r][1] = 0ull; }

    for (int kt = 0; kt < FC; kt += 16) {
        {
            int m = tid >> 1;
            int kb = (tid & 1) * 8;
            int row = row0 + m;
            float4 v0 = make_float4(0.f, 0.f, 0.f, 0.f), v1 = v0;
            if (row < NN) {
                v0 = *(const float4*)&g_Y[(size_t)row * FC + kt + kb];
                v1 = *(const float4*)&g_Y[(size_t)row * FC + kt + kb + 4];
            }
            As[kb + 0][m] = v0.x; As[kb + 1][m] = v0.y; As[kb + 2][m] = v0.z; As[kb + 3][m] = v0.w;
            As[kb + 4][m] = v1.x; As[kb + 5][m] = v1.y; As[kb + 6][m] = v1.z; As[kb + 7][m] = v1.w;
        }
        __syncthreads();
#pragma unroll
        for (int kk = 0; kk < 16; kk++) {
            u64 bb0 = *(const u64*)&W1s[(kt + kk) * FM + tx * 4];
            u64 bb1 = *(const u64*)&W1s[(kt + kk) * FM + tx * 4 + 2];
#pragma unroll
            for (int r = 0; r < 8; r++) {
                u64 aa = dup2(As[kk][ty * 8 + r]);
                ffma2(acc[r][0], aa, bb0);
                ffma2(acc[r][1], aa, bb1);
            }
        }
        __syncthreads();
    }

    float part[8];
    int c0 = tx * 4;
#pragma unroll
    for (int r = 0; r < 8; r++) {
        float t0 = fmaxf(lo2(acc[r][0]) + b1s[c0 + 0], 0.f);
        float t1 = fmaxf(hi2(acc[r][0]) + b1s[c0 + 1], 0.f);
        float t2 = fmaxf(lo2(acc[r][1]) + b1s[c0 + 2], 0.f);
        float t3 = fmaxf(hi2(acc[r][1]) + b1s[c0 + 3], 0.f);
        part[r] = t0 * W2s[c0] + t1 * W2s[c0 + 1] + t2 * W2s[c0 + 2] + t3 * W2s[c0 + 3];
    }
#pragma unroll
    for (int d = 1; d < 16; d <<= 1)
#pragma unroll
        for (int r = 0; r < 8; r++) part[r] += __shfl_xor_sync(0xffffffffu, part[r], d);

    if (tx == 0) {
        float bb = b2[0];
#pragma unroll
        for (int r = 0; r < 8; r++) {
            int row = row0 + ty * 8 + r;
            if (row < NN) out[row] = part[r] + bb;
        }
    }
}

// ---------------- launch ----------------
extern "C" void kernel_launch(void* const* d_in, const int* in_sizes, int n_in,
                              void* d_out, int out_size) {
    const float* x  = (const float*)d_in[0];
    const int*   ei = (const int*)d_in[1];
    const float* ew = (const float*)d_in[2];
    const float* WM = (const float*)d_in[3];
    const float* bM = (const float*)d_in[4];
    const float* WA = (const float*)d_in[5];
    const float* bA = (const float*)d_in[6];
    const float* WS = (const float*)d_in[7];
    const float* bS = (const float*)d_in[8];
    const float* W1 = (const float*)d_in[9];
    const float* b1 = (const float*)d_in[10];
    const float* W2 = (const float*)d_in[11];
    const float* b2 = (const float*)d_in[12];
    float* out = (float*)d_out;

    k_init<<<(NN + 255) / 256, 256>>>(ei);
    k_edges<<<(NE + 255) / 256, 256>>>(ei, ew);
    k_xT<<<dim3(NPAD / 32, KPAD / 32 + 1), 256>>>(x);
    k_pack<<<(KPAD * FC + 255) / 256, 256>>>(WM, WA, WS);
    k_scan<<<1, 1024>>>();
    k_gemm1<<<NPAD / 128, 256>>>(bS);
    k_csr<<<(NE + 255) / 256, 256>>>(ew);
    k_agg<<<NN / 8, 256>>>(bM, bA);
    k_mlp<<<(NN + 127) / 128, 256>>>(W1, b1, W2, b2, out);
}